// round 16
// baseline (speedup 1.0000x reference)
#include <cuda_runtime.h>
#include <cstdint>

#define P 65536
typedef unsigned long long u64;

// ---------------- scratch ----------------
__device__ float g_xu[64 * P];   // upsampled x, channel-major [c][p]
__device__ float g_q[64 * P];    // channel-major [c][p], pre-scaled
__device__ float g_k[64 * P];
__device__ float g_v[64 * P];
__device__ float g_mean[128];    // [0:64] skip, [64:128] xu
__device__ float g_inv[128];
__device__ float g_p1[64 * 64];  // xu partials [c*64+blk]
__device__ float g_p2[64 * 64];
__device__ float g_s1[1024];     // skip partials [c*16+seg]
__device__ float g_s2[1024];

// ---------------- f32x2 helpers ----------------
__device__ __forceinline__ u64 dup2(float v) {
    u64 r; asm("mov.b64 %0,{%1,%1};" : "=l"(r) : "f"(v)); return r;
}
__device__ __forceinline__ void fma2(u64& a, u64 x, u64 y) {
    asm("fma.rn.f32x2 %0,%1,%2,%0;" : "+l"(a) : "l"(x), "l"(y));
}
__device__ __forceinline__ float2 unp2(u64 v) {
    float2 r; asm("mov.b64 {%0,%1},%2;" : "=f"(r.x), "=f"(r.y) : "l"(v)); return r;
}

// ---------------- kernel 1: merged prep (upsample+xu partials | skip partials) ----------------
__global__ __launch_bounds__(256) void k_prep(const float* __restrict__ x,
                                              const float* __restrict__ skip) {
    int t = threadIdx.x;
    int b = blockIdx.x;
    float s = 0.f, s2 = 0.f;

    if (b < 4096) {
        // upsample branch: gid = (c, h, w, zq)
        int gid = b * 256 + t;
        int zq = gid & 3;
        int w  = (gid >> 2) & 63;
        int h  = (gid >> 8) & 63;
        int c  = gid >> 14;

        float ph = (float)h * (31.0f / 63.0f);
        int h0 = min((int)ph, 30); float fh = ph - (float)h0;
        float pw = (float)w * (31.0f / 63.0f);
        int w0 = min((int)pw, 30); float fw = pw - (float)w0;

        const float* xb0 = x + c * 8192 + h0 * 256 + w0 * 8;

        float val[4];
        #pragma unroll
        for (int j = 0; j < 4; j++) {
            int z = zq * 4 + j;
            float pz = (float)z * (7.0f / 15.0f);
            int z0 = min((int)pz, 6);  float fz = pz - (float)z0;

            const float* xb = xb0 + z0;
            float c000 = xb[0],   c001 = xb[1];
            float c010 = xb[8],   c011 = xb[9];
            float c100 = xb[256], c101 = xb[257];
            float c110 = xb[264], c111 = xb[265];

            float a00 = c000 + (c001 - c000) * fz;
            float a01 = c010 + (c011 - c010) * fz;
            float a10 = c100 + (c101 - c100) * fz;
            float a11 = c110 + (c111 - c110) * fz;
            float b0  = a00 + (a01 - a00) * fw;
            float b1  = a10 + (a11 - a10) * fw;
            float v = b0 + (b1 - b0) * fh;
            val[j] = v;
            s += v; s2 += v * v;
        }
        float4 o; o.x = val[0]; o.y = val[1]; o.z = val[2]; o.w = val[3];
        *(float4*)(g_xu + (size_t)c * P + h * 1024 + w * 16 + zq * 4) = o;
    } else {
        // skip-stat branch: bb = (c, segment)
        int bb = b - 4096;
        const float* src = skip + (size_t)(bb >> 4) * P + (bb & 15) * 4096;
        #pragma unroll 4
        for (int i = t; i < 4096; i += 256) {
            float v = src[i];
            s += v; s2 += v * v;
        }
    }

    #pragma unroll
    for (int ofs = 16; ofs; ofs >>= 1) {
        s  += __shfl_down_sync(0xffffffffu, s,  ofs);
        s2 += __shfl_down_sync(0xffffffffu, s2, ofs);
    }
    __shared__ float ws1[8], ws2[8];
    if ((t & 31) == 0) { ws1[t >> 5] = s; ws2[t >> 5] = s2; }
    __syncthreads();
    if (t == 0) {
        float a = 0.f, c2 = 0.f;
        #pragma unroll
        for (int i = 0; i < 8; i++) { a += ws1[i]; c2 += ws2[i]; }
        if (b < 4096) { g_p1[b] = a; g_p2[b] = c2; }            // [c*64 + blk]
        else          { g_s1[b - 4096] = a; g_s2[b - 4096] = c2; }
    }
}

// ---------------- kernel 2: final reduce ----------------
__global__ __launch_bounds__(128) void k_reduce() {
    int t = threadIdx.x;             // [0:64] skip, [64:128] xu
    float s = 0.f, s2 = 0.f;
    if (t < 64) {
        #pragma unroll
        for (int j = 0; j < 16; j++) { s += g_s1[t * 16 + j]; s2 += g_s2[t * 16 + j]; }
    } else {
        int c = t - 64;
        #pragma unroll 8
        for (int j = 0; j < 64; j++) { s += g_p1[c * 64 + j]; s2 += g_p2[c * 64 + j]; }
    }
    float m = s * (1.0f / P);
    float var = s2 * (1.0f / P) - m * m;
    g_mean[t] = m;
    g_inv[t]  = rsqrtf(var + 1e-5f);
}

// ---------------- kernel 3: fused norm + QKV, two-pass (KV then Q) for occupancy ----------------
#define QPAD 68

__global__ __launch_bounds__(256, 4) void k_qkv(
    const float* __restrict__ skip,
    const float* __restrict__ Wq, const float* __restrict__ bq,
    const float* __restrict__ Wk, const float* __restrict__ bk,
    const float* __restrict__ Wv, const float* __restrict__ bv)
{
    __shared__ float sA[64 * QPAD];
    __shared__ float sB[64 * QPAD];
    __shared__ float sC[64 * QPAD];

    int p0 = blockIdx.x * 64;
    int t = threadIdx.x;

    for (int i = t; i < 4096; i += 256) {
        int c = i >> 6, pl = i & 63;
        sA[c * QPAD + pl] = (skip[(size_t)c * P + p0 + pl] - g_mean[c]) * g_inv[c];
        sB[c * QPAD + pl] = (g_xu[(size_t)c * P + p0 + pl] - g_mean[64 + c]) * g_inv[64 + c];
    }
    __syncthreads();

    int cg = t & 31, pg = t >> 5;
    int co = cg * 2;
    const float* bA = sA + pg * 8;
    const float* bB = sB + pg * 8;
    const float sc = 0.35355339059327373f;
    int colbase = pg * 8;

    // ---- pass 1: K and V (read sB only) ----
    {
        u64 ak[2][4], av[2][4];
        #pragma unroll
        for (int j = 0; j < 4; j++) {
            ak[0][j] = 0ull; ak[1][j] = 0ull;
            av[0][j] = 0ull; av[1][j] = 0ull;
        }

        #pragma unroll 2
        for (int c = 0; c < 64; c++) {
            const u64* pb = (const u64*)(bB + c * QPAD);
            u64 b0 = pb[0], b1 = pb[1], b2 = pb[2], b3 = pb[3];

            float2 wk = *(const float2*)(Wk + c * 64 + co);
            float2 wv = *(const float2*)(Wv + c * 64 + co);
            u64 wk0 = dup2(wk.x), wk1 = dup2(wk.y);
            u64 wv0 = dup2(wv.x), wv1 = dup2(wv.y);

            fma2(ak[0][0], b0, wk0); fma2(ak[0][1], b1, wk0); fma2(ak[0][2], b2, wk0); fma2(ak[0][3], b3, wk0);
            fma2(ak[1][0], b0, wk1); fma2(ak[1][1], b1, wk1); fma2(ak[1][2], b2, wk1); fma2(ak[1][3], b3, wk1);
            fma2(av[0][0], b0, wv0); fma2(av[0][1], b1, wv0); fma2(av[0][2], b2, wv0); fma2(av[0][3], b3, wv0);
            fma2(av[1][0], b0, wv1); fma2(av[1][1], b1, wv1); fma2(av[1][2], b2, wv1); fma2(av[1][3], b3, wv1);
        }
        __syncthreads();   // all reads of sB done -> safe to overwrite sB/sC

        float bk0 = bk[co], bk1 = bk[co + 1];
        float bv0 = bv[co], bv1 = bv[co + 1];
        #pragma unroll
        for (int jj = 0; jj < 4; jj++) {
            float2 k0 = unp2(ak[0][jj]), k1 = unp2(ak[1][jj]);
            float2 v0 = unp2(av[0][jj]), v1 = unp2(av[1][jj]);
            float2 v;
            v.x = k0.x + bk0; v.y = k0.y + bk0;
            *(float2*)&sB[co * QPAD + colbase + jj * 2] = v;
            v.x = k1.x + bk1; v.y = k1.y + bk1;
            *(float2*)&sB[(co + 1) * QPAD + colbase + jj * 2] = v;
            v.x = v0.x + bv0; v.y = v0.y + bv0;
            *(float2*)&sC[co * QPAD + colbase + jj * 2] = v;
            v.x = v1.x + bv1; v.y = v1.y + bv1;
            *(float2*)&sC[(co + 1) * QPAD + colbase + jj * 2] = v;
        }
    }

    // ---- pass 2: Q (read sA only) ----
    {
        u64 aq[2][4];
        #pragma unroll
        for (int j = 0; j < 4; j++) { aq[0][j] = 0ull; aq[1][j] = 0ull; }

        #pragma unroll 2
        for (int c = 0; c < 64; c++) {
            const u64* pa = (const u64*)(bA + c * QPAD);
            u64 a0 = pa[0], a1 = pa[1], a2 = pa[2], a3 = pa[3];

            float2 wq = *(const float2*)(Wq + c * 64 + co);
            u64 wq0 = dup2(wq.x), wq1 = dup2(wq.y);

            fma2(aq[0][0], a0, wq0); fma2(aq[0][1], a1, wq0); fma2(aq[0][2], a2, wq0); fma2(aq[0][3], a3, wq0);
            fma2(aq[1][0], a0, wq1); fma2(aq[1][1], a1, wq1); fma2(aq[1][2], a2, wq1); fma2(aq[1][3], a3, wq1);
        }
        __syncthreads();   // all reads of sA done -> safe to overwrite sA

        float bq0 = bq[co], bq1 = bq[co + 1];
        #pragma unroll
        for (int jj = 0; jj < 4; jj++) {
            float2 q0 = unp2(aq[0][jj]), q1 = unp2(aq[1][jj]);
            float2 v;
            v.x = (q0.x + bq0) * sc; v.y = (q0.y + bq0) * sc;
            *(float2*)&sA[co * QPAD + colbase + jj * 2] = v;
            v.x = (q1.x + bq1) * sc; v.y = (q1.y + bq1) * sc;
            *(float2*)&sA[(co + 1) * QPAD + colbase + jj * 2] = v;
        }
    }
    __syncthreads();

    // single store phase: coalesced channel-major STG.128 x 12
    {
        int c = t >> 2, chunk = (t & 3) * 16;
        const float4* srcq = (const float4*)(sA + c * QPAD + chunk);
        const float4* srck = (const float4*)(sB + c * QPAD + chunk);
        const float4* srcv = (const float4*)(sC + c * QPAD + chunk);
        float4* dq = (float4*)(g_q + (size_t)c * P + p0 + chunk);
        float4* dk = (float4*)(g_k + (size_t)c * P + p0 + chunk);
        float4* dv = (float4*)(g_v + (size_t)c * P + p0 + chunk);
        #pragma unroll
        for (int j = 0; j < 4; j++) dq[j] = srcq[j];
        #pragma unroll
        for (int j = 0; j < 4; j++) dk[j] = srck[j];
        #pragma unroll
        for (int j = 0; j < 4; j++) dv[j] = srcv[j];
    }
}

// ---------------- kernel 4: neighborhood attention + fused O-proj (champion, unchanged) ----------------
#define APAD 132

__global__ __launch_bounds__(256, 2) void k_attn(
    const float* __restrict__ Wo, const float* __restrict__ bo,
    const float* __restrict__ rpb, float* __restrict__ out)
{
    __shared__ float sRpb[1000];
    __shared__ float sO[64 * APAD];

    int t = threadIdx.x;
    for (int i = t; i < 1000; i += 256) sRpb[i] = rpb[i];
    __syncthreads();

    int p0 = blockIdx.x * 128;
    int h  = p0 >> 10;
    int w0 = (p0 >> 4) & 63;

    int zq   = t & 3;
    int lw   = (t >> 2) & 7;
    int head = t >> 5;
    int w    = w0 + lw;
    int c0   = head * 8;
    int zb   = zq * 4;

    int sh = min(max(h - 1, 0), 61);
    int sw = min(max(w - 1, 0), 61);
    bool z0e = (zq == 0), z3e = (zq == 3);
    int rbh = sh - h + 2, rbw = sw - w + 2;

    float4 q[8];
    {
        const float* qb = g_q + h * 1024 + w * 16 + zb;
        #pragma unroll
        for (int i = 0; i < 8; i++) q[i] = *(const float4*)(qb + (size_t)(c0 + i) * P);
    }

    float o[8][4];
    #pragma unroll
    for (int i = 0; i < 8; i++)
        #pragma unroll
        for (int j = 0; j < 4; j++) o[i][j] = 0.f;
    float ssum[4] = {0.f, 0.f, 0.f, 0.f};

    #pragma unroll
    for (int a = 0; a < 3; a++) {
        #pragma unroll
        for (int b = 0; b < 3; b++) {
            int rowoff = (sh + a) * 1024 + (sw + b) * 16 + zb;
            const float* rp = sRpb + head * 125 + (rbh + a) * 25 + (rbw + b) * 5;

            float lg[3][4];
            #pragma unroll
            for (int cz = 0; cz < 3; cz++) {
                float bi = rp[1 + cz];
                lg[cz][0] = z0e ? rp[2 + cz] : bi;
                lg[cz][1] = bi;
                lg[cz][2] = bi;
                lg[cz][3] = z3e ? rp[cz] : bi;
            }

            #pragma unroll
            for (int i = 0; i < 8; i++) {
                float4 f = *(const float4*)(g_k + (size_t)(c0 + i) * P + rowoff);
                float m1 = __shfl_up_sync(0xffffffffu, f.w, 1);
                float p4 = __shfl_down_sync(0xffffffffu, f.x, 1);
                float wn[6] = {m1, f.x, f.y, f.z, f.w, p4};
                #pragma unroll
                for (int cz = 0; cz < 3; cz++) {
                    float v0 = z0e ? wn[1 + cz] : wn[cz];
                    float v3 = z3e ? wn[2 + cz] : wn[3 + cz];
                    lg[cz][0] = fmaf(q[i].x, v0,          lg[cz][0]);
                    lg[cz][1] = fmaf(q[i].y, wn[1 + cz],  lg[cz][1]);
                    lg[cz][2] = fmaf(q[i].z, wn[2 + cz],  lg[cz][2]);
                    lg[cz][3] = fmaf(q[i].w, v3,          lg[cz][3]);
                }
            }

            #pragma unroll
            for (int cz = 0; cz < 3; cz++) {
                #pragma unroll
                for (int j = 0; j < 4; j++) {
                    float e = __expf(lg[cz][j]);
                    lg[cz][j] = e;
                    ssum[j] += e;
                }
            }

            #pragma unroll
            for (int i = 0; i < 8; i++) {
                float4 f = *(const float4*)(g_v + (size_t)(c0 + i) * P + rowoff);
                float m1 = __shfl_up_sync(0xffffffffu, f.w, 1);
                float p4 = __shfl_down_sync(0xffffffffu, f.x, 1);
                float wn[6] = {m1, f.x, f.y, f.z, f.w, p4};
                #pragma unroll
                for (int cz = 0; cz < 3; cz++) {
                    float v0 = z0e ? wn[1 + cz] : wn[cz];
                    float v3 = z3e ? wn[2 + cz] : wn[3 + cz];
                    o[i][0] = fmaf(lg[cz][0], v0,         o[i][0]);
                    o[i][1] = fmaf(lg[cz][1], wn[1 + cz], o[i][1]);
                    o[i][2] = fmaf(lg[cz][2], wn[2 + cz], o[i][2]);
                    o[i][3] = fmaf(lg[cz][3], v3,         o[i][3]);
                }
            }
        }
    }

    float r0 = 1.0f / ssum[0], r1 = 1.0f / ssum[1];
    float r2 = 1.0f / ssum[2], r3 = 1.0f / ssum[3];
    int pl = lw * 16 + zb;
    #pragma unroll
    for (int i = 0; i < 8; i++) {
        float4 v;
        v.x = o[i][0] * r0; v.y = o[i][1] * r1;
        v.z = o[i][2] * r2; v.w = o[i][3] * r3;
        *(float4*)(sO + (c0 + i) * APAD + pl) = v;
    }
    __syncthreads();

    int pp = t & 63;
    int cg = t >> 6;
    int cob = cg * 16;

    u64 acc[8][2];
    #pragma unroll
    for (int i = 0; i < 8; i++) { acc[i][0] = 0ull; acc[i][1] = 0ull; }

    #pragma unroll 2
    for (int c = 0; c < 64; c++) {
        float2 in = *(const float2*)&sO[c * APAD + pp * 2];
        u64 i0 = dup2(in.x), i1 = dup2(in.y);
        ulonglong2 wA = *(const ulonglong2*)(Wo + c * 64 + cob);
        ulonglong2 wB = *(const ulonglong2*)(Wo + c * 64 + cob + 4);
        ulonglong2 wC = *(const ulonglong2*)(Wo + c * 64 + cob + 8);
        ulonglong2 wD = *(const ulonglong2*)(Wo + c * 64 + cob + 12);
        fma2(acc[0][0], wA.x, i0); fma2(acc[0][1], wA.x, i1);
        fma2(acc[1][0], wA.y, i0); fma2(acc[1][1], wA.y, i1);
        fma2(acc[2][0], wB.x, i0); fma2(acc[2][1], wB.x, i1);
        fma2(acc[3][0], wB.y, i0); fma2(acc[3][1], wB.y, i1);
        fma2(acc[4][0], wC.x, i0); fma2(acc[4][1], wC.x, i1);
        fma2(acc[5][0], wC.y, i0); fma2(acc[5][1], wC.y, i1);
        fma2(acc[6][0], wD.x, i0); fma2(acc[6][1], wD.x, i1);
        fma2(acc[7][0], wD.y, i0); fma2(acc[7][1], wD.y, i1);
    }

    int p = p0 + pp * 2;
    #pragma unroll
    for (int cop = 0; cop < 8; cop++) {
        int ch = cob + cop * 2;
        float2 lo = unp2(acc[cop][0]);
        float2 hi = unp2(acc[cop][1]);
        float b0v = bo[ch], b1v = bo[ch + 1];
        float2 s0; s0.x = lo.x + b0v; s0.y = hi.x + b0v;
        float2 s1; s1.x = lo.y + b1v; s1.y = hi.y + b1v;
        *(float2*)(out + (size_t)ch * P + p) = s0;
        *(float2*)(out + (size_t)(ch + 1) * P + p) = s1;
    }
}

// ---------------- launch ----------------
extern "C" void kernel_launch(void* const* d_in, const int* in_sizes, int n_in,
                              void* d_out, int out_size) {
    const float* x    = (const float*)d_in[0];
    const float* skip = (const float*)d_in[1];
    const float* Wq   = (const float*)d_in[2];
    const float* bq   = (const float*)d_in[3];
    const float* Wk   = (const float*)d_in[4];
    const float* bk   = (const float*)d_in[5];
    const float* Wv   = (const float*)d_in[6];
    const float* bv   = (const float*)d_in[7];
    const float* Wo   = (const float*)d_in[8];
    const float* bo   = (const float*)d_in[9];
    const float* rpb  = (const float*)d_in[10];
    float* out = (float*)d_out;

    k_prep<<<5120, 256>>>(x, skip);
    k_reduce<<<1, 128>>>();
    k_qkv<<<1024, 256>>>(skip, Wq, bq, Wk, bk, Wv, bv);
    k_attn<<<512, 256>>>(Wo, bo, rpb, out);
}

// round 17
// speedup vs baseline: 1.0160x; 1.0160x over previous
#include <cuda_runtime.h>
#include <cstdint>

#define P 65536
typedef unsigned long long u64;

// ---------------- scratch ----------------
__device__ float g_xu[64 * P];   // upsampled x, channel-major [c][p]
__device__ float g_q[64 * P];    // channel-major [c][p], pre-scaled
__device__ float g_k[64 * P];
__device__ float g_v[64 * P];
__device__ float g_mean[128];    // [0:64] skip, [64:128] xu
__device__ float g_inv[128];
__device__ float g_p1[64 * 64];  // xu partials [c*64+blk]
__device__ float g_p2[64 * 64];
__device__ float g_s1[1024];     // skip partials [c*16+seg]
__device__ float g_s2[1024];

// ---------------- f32x2 helpers ----------------
__device__ __forceinline__ u64 dup2(float v) {
    u64 r; asm("mov.b64 %0,{%1,%1};" : "=l"(r) : "f"(v)); return r;
}
__device__ __forceinline__ void fma2(u64& a, u64 x, u64 y) {
    asm("fma.rn.f32x2 %0,%1,%2,%0;" : "+l"(a) : "l"(x), "l"(y));
}
__device__ __forceinline__ float2 unp2(u64 v) {
    float2 r; asm("mov.b64 {%0,%1},%2;" : "=f"(r.x), "=f"(r.y) : "l"(v)); return r;
}

// ---------------- kernel 1: merged prep (upsample+xu partials | skip partials) ----------------
__global__ __launch_bounds__(256) void k_prep(const float* __restrict__ x,
                                              const float* __restrict__ skip) {
    int t = threadIdx.x;
    int b = blockIdx.x;
    float s = 0.f, s2 = 0.f;

    if (b < 4096) {
        // upsample branch: gid = (c, h, w, zq)
        int gid = b * 256 + t;
        int zq = gid & 3;
        int w  = (gid >> 2) & 63;
        int h  = (gid >> 8) & 63;
        int c  = gid >> 14;

        float ph = (float)h * (31.0f / 63.0f);
        int h0 = min((int)ph, 30); float fh = ph - (float)h0;
        float pw = (float)w * (31.0f / 63.0f);
        int w0 = min((int)pw, 30); float fw = pw - (float)w0;

        const float* xb0 = x + c * 8192 + h0 * 256 + w0 * 8;

        float val[4];
        #pragma unroll
        for (int j = 0; j < 4; j++) {
            int z = zq * 4 + j;
            float pz = (float)z * (7.0f / 15.0f);
            int z0 = min((int)pz, 6);  float fz = pz - (float)z0;

            const float* xb = xb0 + z0;
            float c000 = xb[0],   c001 = xb[1];
            float c010 = xb[8],   c011 = xb[9];
            float c100 = xb[256], c101 = xb[257];
            float c110 = xb[264], c111 = xb[265];

            float a00 = c000 + (c001 - c000) * fz;
            float a01 = c010 + (c011 - c010) * fz;
            float a10 = c100 + (c101 - c100) * fz;
            float a11 = c110 + (c111 - c110) * fz;
            float b0  = a00 + (a01 - a00) * fw;
            float b1  = a10 + (a11 - a10) * fw;
            float v = b0 + (b1 - b0) * fh;
            val[j] = v;
            s += v; s2 += v * v;
        }
        float4 o; o.x = val[0]; o.y = val[1]; o.z = val[2]; o.w = val[3];
        *(float4*)(g_xu + (size_t)c * P + h * 1024 + w * 16 + zq * 4) = o;
    } else {
        // skip-stat branch: bb = (c, segment)
        int bb = b - 4096;
        const float* src = skip + (size_t)(bb >> 4) * P + (bb & 15) * 4096;
        #pragma unroll 4
        for (int i = t; i < 4096; i += 256) {
            float v = src[i];
            s += v; s2 += v * v;
        }
    }

    #pragma unroll
    for (int ofs = 16; ofs; ofs >>= 1) {
        s  += __shfl_down_sync(0xffffffffu, s,  ofs);
        s2 += __shfl_down_sync(0xffffffffu, s2, ofs);
    }
    __shared__ float ws1[8], ws2[8];
    if ((t & 31) == 0) { ws1[t >> 5] = s; ws2[t >> 5] = s2; }
    __syncthreads();
    if (t == 0) {
        float a = 0.f, c2 = 0.f;
        #pragma unroll
        for (int i = 0; i < 8; i++) { a += ws1[i]; c2 += ws2[i]; }
        if (b < 4096) { g_p1[b] = a; g_p2[b] = c2; }            // [c*64 + blk]
        else          { g_s1[b - 4096] = a; g_s2[b - 4096] = c2; }
    }
}

// ---------------- kernel 2: final reduce ----------------
__global__ __launch_bounds__(128) void k_reduce() {
    int t = threadIdx.x;             // [0:64] skip, [64:128] xu
    float s = 0.f, s2 = 0.f;
    if (t < 64) {
        #pragma unroll
        for (int j = 0; j < 16; j++) { s += g_s1[t * 16 + j]; s2 += g_s2[t * 16 + j]; }
    } else {
        int c = t - 64;
        #pragma unroll 8
        for (int j = 0; j < 64; j++) { s += g_p1[c * 64 + j]; s2 += g_p2[c * 64 + j]; }
    }
    float m = s * (1.0f / P);
    float var = s2 * (1.0f / P) - m * m;
    g_mean[t] = m;
    g_inv[t]  = rsqrtf(var + 1e-5f);
}

// ---------------- kernel 3: fused norm + QKV, two-pass (KV then Q) for occupancy ----------------
#define QPAD 68

__global__ __launch_bounds__(256, 4) void k_qkv(
    const float* __restrict__ skip,
    const float* __restrict__ Wq, const float* __restrict__ bq,
    const float* __restrict__ Wk, const float* __restrict__ bk,
    const float* __restrict__ Wv, const float* __restrict__ bv)
{
    __shared__ float sA[64 * QPAD];
    __shared__ float sB[64 * QPAD];
    __shared__ float sC[64 * QPAD];

    int p0 = blockIdx.x * 64;
    int t = threadIdx.x;

    for (int i = t; i < 4096; i += 256) {
        int c = i >> 6, pl = i & 63;
        sA[c * QPAD + pl] = (skip[(size_t)c * P + p0 + pl] - g_mean[c]) * g_inv[c];
        sB[c * QPAD + pl] = (g_xu[(size_t)c * P + p0 + pl] - g_mean[64 + c]) * g_inv[64 + c];
    }
    __syncthreads();

    int cg = t & 31, pg = t >> 5;
    int co = cg * 2;
    const float* bA = sA + pg * 8;
    const float* bB = sB + pg * 8;
    const float sc = 0.35355339059327373f;
    int colbase = pg * 8;

    // ---- pass 1: K and V (read sB only) ----
    {
        u64 ak[2][4], av[2][4];
        #pragma unroll
        for (int j = 0; j < 4; j++) {
            ak[0][j] = 0ull; ak[1][j] = 0ull;
            av[0][j] = 0ull; av[1][j] = 0ull;
        }

        #pragma unroll 2
        for (int c = 0; c < 64; c++) {
            const u64* pb = (const u64*)(bB + c * QPAD);
            u64 b0 = pb[0], b1 = pb[1], b2 = pb[2], b3 = pb[3];

            float2 wk = *(const float2*)(Wk + c * 64 + co);
            float2 wv = *(const float2*)(Wv + c * 64 + co);
            u64 wk0 = dup2(wk.x), wk1 = dup2(wk.y);
            u64 wv0 = dup2(wv.x), wv1 = dup2(wv.y);

            fma2(ak[0][0], b0, wk0); fma2(ak[0][1], b1, wk0); fma2(ak[0][2], b2, wk0); fma2(ak[0][3], b3, wk0);
            fma2(ak[1][0], b0, wk1); fma2(ak[1][1], b1, wk1); fma2(ak[1][2], b2, wk1); fma2(ak[1][3], b3, wk1);
            fma2(av[0][0], b0, wv0); fma2(av[0][1], b1, wv0); fma2(av[0][2], b2, wv0); fma2(av[0][3], b3, wv0);
            fma2(av[1][0], b0, wv1); fma2(av[1][1], b1, wv1); fma2(av[1][2], b2, wv1); fma2(av[1][3], b3, wv1);
        }
        __syncthreads();   // all reads of sB done -> safe to overwrite sB/sC

        float bk0 = bk[co], bk1 = bk[co + 1];
        float bv0 = bv[co], bv1 = bv[co + 1];
        #pragma unroll
        for (int jj = 0; jj < 4; jj++) {
            float2 k0 = unp2(ak[0][jj]), k1 = unp2(ak[1][jj]);
            float2 v0 = unp2(av[0][jj]), v1 = unp2(av[1][jj]);
            float2 v;
            v.x = k0.x + bk0; v.y = k0.y + bk0;
            *(float2*)&sB[co * QPAD + colbase + jj * 2] = v;
            v.x = k1.x + bk1; v.y = k1.y + bk1;
            *(float2*)&sB[(co + 1) * QPAD + colbase + jj * 2] = v;
            v.x = v0.x + bv0; v.y = v0.y + bv0;
            *(float2*)&sC[co * QPAD + colbase + jj * 2] = v;
            v.x = v1.x + bv1; v.y = v1.y + bv1;
            *(float2*)&sC[(co + 1) * QPAD + colbase + jj * 2] = v;
        }
    }

    // ---- pass 2: Q (read sA only) ----
    {
        u64 aq[2][4];
        #pragma unroll
        for (int j = 0; j < 4; j++) { aq[0][j] = 0ull; aq[1][j] = 0ull; }

        #pragma unroll 2
        for (int c = 0; c < 64; c++) {
            const u64* pa = (const u64*)(bA + c * QPAD);
            u64 a0 = pa[0], a1 = pa[1], a2 = pa[2], a3 = pa[3];

            float2 wq = *(const float2*)(Wq + c * 64 + co);
            u64 wq0 = dup2(wq.x), wq1 = dup2(wq.y);

            fma2(aq[0][0], a0, wq0); fma2(aq[0][1], a1, wq0); fma2(aq[0][2], a2, wq0); fma2(aq[0][3], a3, wq0);
            fma2(aq[1][0], a0, wq1); fma2(aq[1][1], a1, wq1); fma2(aq[1][2], a2, wq1); fma2(aq[1][3], a3, wq1);
        }
        __syncthreads();   // all reads of sA done -> safe to overwrite sA

        float bq0 = bq[co], bq1 = bq[co + 1];
        #pragma unroll
        for (int jj = 0; jj < 4; jj++) {
            float2 q0 = unp2(aq[0][jj]), q1 = unp2(aq[1][jj]);
            float2 v;
            v.x = (q0.x + bq0) * sc; v.y = (q0.y + bq0) * sc;
            *(float2*)&sA[co * QPAD + colbase + jj * 2] = v;
            v.x = (q1.x + bq1) * sc; v.y = (q1.y + bq1) * sc;
            *(float2*)&sA[(co + 1) * QPAD + colbase + jj * 2] = v;
        }
    }
    __syncthreads();

    // single store phase: coalesced channel-major STG.128 x 12
    {
        int c = t >> 2, chunk = (t & 3) * 16;
        const float4* srcq = (const float4*)(sA + c * QPAD + chunk);
        const float4* srck = (const float4*)(sB + c * QPAD + chunk);
        const float4* srcv = (const float4*)(sC + c * QPAD + chunk);
        float4* dq = (float4*)(g_q + (size_t)c * P + p0 + chunk);
        float4* dk = (float4*)(g_k + (size_t)c * P + p0 + chunk);
        float4* dv = (float4*)(g_v + (size_t)c * P + p0 + chunk);
        #pragma unroll
        for (int j = 0; j < 4; j++) dq[j] = srcq[j];
        #pragma unroll
        for (int j = 0; j < 4; j++) dk[j] = srck[j];
        #pragma unroll
        for (int j = 0; j < 4; j++) dv[j] = srcv[j];
    }
}

// ---------------- kernel 4: neighborhood attention + fused O-proj (champion, unchanged) ----------------
#define APAD 132

__global__ __launch_bounds__(256, 2) void k_attn(
    const float* __restrict__ Wo, const float* __restrict__ bo,
    const float* __restrict__ rpb, float* __restrict__ out)
{
    __shared__ float sRpb[1000];
    __shared__ float sO[64 * APAD];

    int t = threadIdx.x;
    for (int i = t; i < 1000; i += 256) sRpb[i] = rpb[i];
    __syncthreads();

    int p0 = blockIdx.x * 128;
    int h  = p0 >> 10;
    int w0 = (p0 >> 4) & 63;

    int zq   = t & 3;
    int lw   = (t >> 2) & 7;
    int head = t >> 5;
    int w    = w0 + lw;
    int c0   = head * 8;
    int zb   = zq * 4;

    int sh = min(max(h - 1, 0), 61);
    int sw = min(max(w - 1, 0), 61);
    bool z0e = (zq == 0), z3e = (zq == 3);
    int rbh = sh - h + 2, rbw = sw - w + 2;

    float4 q[8];
    {
        const float* qb = g_q + h * 1024 + w * 16 + zb;
        #pragma unroll
        for (int i = 0; i < 8; i++) q[i] = *(const float4*)(qb + (size_t)(c0 + i) * P);
    }

    float o[8][4];
    #pragma unroll
    for (int i = 0; i < 8; i++)
        #pragma unroll
        for (int j = 0; j < 4; j++) o[i][j] = 0.f;
    float ssum[4] = {0.f, 0.f, 0.f, 0.f};

    #pragma unroll
    for (int a = 0; a < 3; a++) {
        #pragma unroll
        for (int b = 0; b < 3; b++) {
            int rowoff = (sh + a) * 1024 + (sw + b) * 16 + zb;
            const float* rp = sRpb + head * 125 + (rbh + a) * 25 + (rbw + b) * 5;

            float lg[3][4];
            #pragma unroll
            for (int cz = 0; cz < 3; cz++) {
                float bi = rp[1 + cz];
                lg[cz][0] = z0e ? rp[2 + cz] : bi;
                lg[cz][1] = bi;
                lg[cz][2] = bi;
                lg[cz][3] = z3e ? rp[cz] : bi;
            }

            #pragma unroll
            for (int i = 0; i < 8; i++) {
                float4 f = *(const float4*)(g_k + (size_t)(c0 + i) * P + rowoff);
                float m1 = __shfl_up_sync(0xffffffffu, f.w, 1);
                float p4 = __shfl_down_sync(0xffffffffu, f.x, 1);
                float wn[6] = {m1, f.x, f.y, f.z, f.w, p4};
                #pragma unroll
                for (int cz = 0; cz < 3; cz++) {
                    float v0 = z0e ? wn[1 + cz] : wn[cz];
                    float v3 = z3e ? wn[2 + cz] : wn[3 + cz];
                    lg[cz][0] = fmaf(q[i].x, v0,          lg[cz][0]);
                    lg[cz][1] = fmaf(q[i].y, wn[1 + cz],  lg[cz][1]);
                    lg[cz][2] = fmaf(q[i].z, wn[2 + cz],  lg[cz][2]);
                    lg[cz][3] = fmaf(q[i].w, v3,          lg[cz][3]);
                }
            }

            #pragma unroll
            for (int cz = 0; cz < 3; cz++) {
                #pragma unroll
                for (int j = 0; j < 4; j++) {
                    float e = __expf(lg[cz][j]);
                    lg[cz][j] = e;
                    ssum[j] += e;
                }
            }

            #pragma unroll
            for (int i = 0; i < 8; i++) {
                float4 f = *(const float4*)(g_v + (size_t)(c0 + i) * P + rowoff);
                float m1 = __shfl_up_sync(0xffffffffu, f.w, 1);
                float p4 = __shfl_down_sync(0xffffffffu, f.x, 1);
                float wn[6] = {m1, f.x, f.y, f.z, f.w, p4};
                #pragma unroll
                for (int cz = 0; cz < 3; cz++) {
                    float v0 = z0e ? wn[1 + cz] : wn[cz];
                    float v3 = z3e ? wn[2 + cz] : wn[3 + cz];
                    o[i][0] = fmaf(lg[cz][0], v0,         o[i][0]);
                    o[i][1] = fmaf(lg[cz][1], wn[1 + cz], o[i][1]);
                    o[i][2] = fmaf(lg[cz][2], wn[2 + cz], o[i][2]);
                    o[i][3] = fmaf(lg[cz][3], v3,         o[i][3]);
                }
            }
        }
    }

    float r0 = 1.0f / ssum[0], r1 = 1.0f / ssum[1];
    float r2 = 1.0f / ssum[2], r3 = 1.0f / ssum[3];
    int pl = lw * 16 + zb;
    #pragma unroll
    for (int i = 0; i < 8; i++) {
        float4 v;
        v.x = o[i][0] * r0; v.y = o[i][1] * r1;
        v.z = o[i][2] * r2; v.w = o[i][3] * r3;
        *(float4*)(sO + (c0 + i) * APAD + pl) = v;
    }
    __syncthreads();

    int pp = t & 63;
    int cg = t >> 6;
    int cob = cg * 16;

    u64 acc[8][2];
    #pragma unroll
    for (int i = 0; i < 8; i++) { acc[i][0] = 0ull; acc[i][1] = 0ull; }

    #pragma unroll 2
    for (int c = 0; c < 64; c++) {
        float2 in = *(const float2*)&sO[c * APAD + pp * 2];
        u64 i0 = dup2(in.x), i1 = dup2(in.y);
        ulonglong2 wA = *(const ulonglong2*)(Wo + c * 64 + cob);
        ulonglong2 wB = *(const ulonglong2*)(Wo + c * 64 + cob + 4);
        ulonglong2 wC = *(const ulonglong2*)(Wo + c * 64 + cob + 8);
        ulonglong2 wD = *(const ulonglong2*)(Wo + c * 64 + cob + 12);
        fma2(acc[0][0], wA.x, i0); fma2(acc[0][1], wA.x, i1);
        fma2(acc[1][0], wA.y, i0); fma2(acc[1][1], wA.y, i1);
        fma2(acc[2][0], wB.x, i0); fma2(acc[2][1], wB.x, i1);
        fma2(acc[3][0], wB.y, i0); fma2(acc[3][1], wB.y, i1);
        fma2(acc[4][0], wC.x, i0); fma2(acc[4][1], wC.x, i1);
        fma2(acc[5][0], wC.y, i0); fma2(acc[5][1], wC.y, i1);
        fma2(acc[6][0], wD.x, i0); fma2(acc[6][1], wD.x, i1);
        fma2(acc[7][0], wD.y, i0); fma2(acc[7][1], wD.y, i1);
    }

    int p = p0 + pp * 2;
    #pragma unroll
    for (int cop = 0; cop < 8; cop++) {
        int ch = cob + cop * 2;
        float2 lo = unp2(acc[cop][0]);
        float2 hi = unp2(acc[cop][1]);
        float b0v = bo[ch], b1v = bo[ch + 1];
        float2 s0; s0.x = lo.x + b0v; s0.y = hi.x + b0v;
        float2 s1; s1.x = lo.y + b1v; s1.y = hi.y + b1v;
        *(float2*)(out + (size_t)ch * P + p) = s0;
        *(float2*)(out + (size_t)(ch + 1) * P + p) = s1;
    }
}

// ---------------- launch ----------------
extern "C" void kernel_launch(void* const* d_in, const int* in_sizes, int n_in,
                              void* d_out, int out_size) {
    const float* x    = (const float*)d_in[0];
    const float* skip = (const float*)d_in[1];
    const float* Wq   = (const float*)d_in[2];
    const float* bq   = (const float*)d_in[3];
    const float* Wk   = (const float*)d_in[4];
    const float* bk   = (const float*)d_in[5];
    const float* Wv   = (const float*)d_in[6];
    const float* bv   = (const float*)d_in[7];
    const float* Wo   = (const float*)d_in[8];
    const float* bo   = (const float*)d_in[9];
    const float* rpb  = (const float*)d_in[10];
    float* out = (float*)d_out;

    k_prep<<<5120, 256>>>(x, skip);
    k_reduce<<<1, 128>>>();
    k_qkv<<<1024, 256>>>(skip, Wq, bq, Wk, bk, Wv, bv);
    k_attn<<<512, 256>>>(Wo, bo, rpb, out);
}